// round 9
// baseline (speedup 1.0000x reference)
#include <cuda_runtime.h>
#include <cuda_bf16.h>
#include <cstdint>

// Problem constants
#define Bn   2
#define Sn   2048
#define Dm   1024
#define Hn   16
#define DKc  64
#define Mrows 4096          // B*S
#define TC   3072           // 3*Dm

// Scratch (allocation-free: __device__ globals)
__device__ __nv_bfloat16 g_qh[(size_t)Mrows * TC];  // qkv hi
__device__ __nv_bfloat16 g_ql[(size_t)Mrows * TC];  // qkv lo
__device__ __nv_bfloat16 g_ah[(size_t)Mrows * Dm];  // A hi (x-split, then attn out)
__device__ __nv_bfloat16 g_al[(size_t)Mrows * Dm];  // A lo
__device__ __nv_bfloat16 g_bh[(size_t)TC * Dm];     // B^T hi
__device__ __nv_bfloat16 g_bl[(size_t)TC * Dm];     // B^T lo

// ---------------------------------------------------------------------------
// PTX helpers (baseline-PTX only: cp.async, ldmatrix, mma.sync)
// ---------------------------------------------------------------------------
__device__ __forceinline__ uint32_t smem_u32(const void* p) {
    return (uint32_t)__cvta_generic_to_shared(p);
}
#define CP_ASYNC16(dst, src) \
    asm volatile("cp.async.cg.shared.global [%0], [%1], 16;" :: "r"(dst), "l"(src))
#define CP_COMMIT() asm volatile("cp.async.commit_group;" ::: "memory")
#define CP_WAIT2()  asm volatile("cp.async.wait_group 2;" ::: "memory")
#define CP_WAIT1()  asm volatile("cp.async.wait_group 1;" ::: "memory")
#define CP_WAIT0()  asm volatile("cp.async.wait_group 0;" ::: "memory")

__device__ __forceinline__ void ldsm4(uint32_t* r, uint32_t addr) {
    asm volatile("ldmatrix.sync.aligned.m8n8.x4.shared.b16 {%0,%1,%2,%3}, [%4];"
        : "=r"(r[0]), "=r"(r[1]), "=r"(r[2]), "=r"(r[3]) : "r"(addr));
}
__device__ __forceinline__ void ldsm4t(uint32_t* r, uint32_t addr) {
    asm volatile("ldmatrix.sync.aligned.m8n8.x4.trans.shared.b16 {%0,%1,%2,%3}, [%4];"
        : "=r"(r[0]), "=r"(r[1]), "=r"(r[2]), "=r"(r[3]) : "r"(addr));
}
__device__ __forceinline__ void mma16816(float* d, const uint32_t* a, const uint32_t* b) {
    asm volatile(
        "mma.sync.aligned.m16n8k16.row.col.f32.bf16.bf16.f32 "
        "{%0,%1,%2,%3}, {%4,%5,%6,%7}, {%8,%9}, {%0,%1,%2,%3};"
        : "+f"(d[0]), "+f"(d[1]), "+f"(d[2]), "+f"(d[3])
        : "r"(a[0]), "r"(a[1]), "r"(a[2]), "r"(a[3]), "r"(b[0]), "r"(b[1]));
}
__device__ __forceinline__ float ex2(float x) {
    float r; asm("ex2.approx.f32 %0, %1;" : "=f"(r) : "f"(x)); return r;
}
// pack two f32 -> bf16x2 (first arg in low half)
__device__ __forceinline__ uint32_t pk_bf2(float lo, float hi) {
    uint32_t r;
    asm("cvt.rn.bf16x2.f32 %0, %1, %2;" : "=r"(r) : "f"(hi), "f"(lo));
    return r;
}
__device__ __forceinline__ float bf16_rt(float v) {   // round-trip through bf16
    return __bfloat162float(__float2bfloat16(v));
}

// ---------------------------------------------------------------------------
// fp32 -> bf16 hi/lo split (straight copy)
// ---------------------------------------------------------------------------
__global__ void split_kernel(const float* __restrict__ in,
                             __nv_bfloat16* __restrict__ hi,
                             __nv_bfloat16* __restrict__ lo, int n4)
{
    int i = blockIdx.x * blockDim.x + threadIdx.x;
    if (i >= n4) return;
    float4 v = ((const float4*)in)[i];
    float vv[4] = {v.x, v.y, v.z, v.w};
    uint32_t h2[2], l2[2];
#pragma unroll
    for (int p = 0; p < 2; p++) {
        h2[p] = pk_bf2(vv[2*p], vv[2*p+1]);
        __nv_bfloat162 hh = *(__nv_bfloat162*)&h2[p];
        float f0 = __bfloat162float(hh.x), f1 = __bfloat162float(hh.y);
        l2[p] = pk_bf2(vv[2*p] - f0, vv[2*p+1] - f1);
    }
    ((uint32_t*)hi)[2*i]   = h2[0];
    ((uint32_t*)hi)[2*i+1] = h2[1];
    ((uint32_t*)lo)[2*i]   = l2[0];
    ((uint32_t*)lo)[2*i+1] = l2[1];
}

// ---------------------------------------------------------------------------
// fp32 [K][N] -> bf16 hi/lo [N][K] (transpose + split), 32x32 tiles
// ---------------------------------------------------------------------------
__global__ void transpose_split_kernel(const float* __restrict__ in,
                                       __nv_bfloat16* __restrict__ hi,
                                       __nv_bfloat16* __restrict__ lo,
                                       int K, int N)
{
    __shared__ float t[32][33];
    int bx = blockIdx.x << 5;
    int by = blockIdx.y << 5;
    int x = threadIdx.x;
    int y = threadIdx.y;
#pragma unroll
    for (int i = 0; i < 32; i += 8)
        t[y + i][x] = in[(size_t)(by + y + i) * N + bx + x];
    __syncthreads();
#pragma unroll
    for (int i = 0; i < 32; i += 8) {
        float v = t[x][y + i];
        float h = bf16_rt(v);
        size_t o = (size_t)(bx + y + i) * K + by + x;
        hi[o] = __float2bfloat16(v);
        lo[o] = __float2bfloat16(v - h);
    }
}

// ---------------------------------------------------------------------------
// HMMA bf16-split GEMM: C[M,N] = A[M,K] @ BT[N,K]^T + bias
// 128x128x32 CTA tile, 8 warps of 64x32, 4-stage cp.async pipeline.
// SPLIT_OUT=1: write hi/lo bf16 (Ch/Cl); else fp32 C.  (unchanged from R6)
// ---------------------------------------------------------------------------
#define SUB_BYTES  8192
#define STAGE_BYTES (4 * SUB_BYTES)
#define NSTAGE 4
#define GEMM_DSMEM (NSTAGE * STAGE_BYTES)  // 128 KB

__device__ __forceinline__ void load_chunk(
    uint32_t so, int tid, int chunk,
    const __nv_bfloat16* __restrict__ Ah, const __nv_bfloat16* __restrict__ Al,
    const __nv_bfloat16* __restrict__ Bh, const __nv_bfloat16* __restrict__ Bl,
    int brow, int bcol, int K)
{
    const int k0 = chunk << 5;
#pragma unroll
    for (int p = 0; p < 2; p++) {
        int r   = (tid >> 2) + (p << 6);
        int c16 = tid & 3;
        uint32_t dst = so + r * 64 + ((c16 ^ ((r >> 1) & 3)) << 4);
        size_t ga = (size_t)(brow + r) * K + k0 + (c16 << 3);
        size_t gb = (size_t)(bcol + r) * K + k0 + (c16 << 3);
        CP_ASYNC16(dst,                 Ah + ga);
        CP_ASYNC16(dst + SUB_BYTES,     Al + ga);
        CP_ASYNC16(dst + 2 * SUB_BYTES, Bh + gb);
        CP_ASYNC16(dst + 3 * SUB_BYTES, Bl + gb);
    }
}

template<int SPLIT_OUT>
__global__ __launch_bounds__(256, 1)
void gemm_bf16x3(const __nv_bfloat16* __restrict__ Ah, const __nv_bfloat16* __restrict__ Al,
                 const __nv_bfloat16* __restrict__ Bh, const __nv_bfloat16* __restrict__ Bl,
                 const float* __restrict__ bias, float* __restrict__ C,
                 __nv_bfloat16* __restrict__ Ch, __nv_bfloat16* __restrict__ Cl,
                 int N, int K)
{
    extern __shared__ char dsmem_raw[];
    const uint32_t sb = smem_u32(dsmem_raw);

    const int tid  = threadIdx.x;
    const int wid  = tid >> 5;
    const int lane = tid & 31;
    const int brow = blockIdx.y << 7;
    const int bcol = blockIdx.x << 7;
    const int NCHUNK = K >> 5;

    const int m0 = (wid & 1) << 6;
    const int n0 = (wid >> 1) << 5;

    float acc[4][4][4];
#pragma unroll
    for (int mt = 0; mt < 4; mt++)
#pragma unroll
        for (int nt = 0; nt < 4; nt++)
#pragma unroll
            for (int e = 0; e < 4; e++) acc[mt][nt][e] = 0.f;

    int arow[4], asel[4];
#pragma unroll
    for (int mt = 0; mt < 4; mt++) {
        arow[mt] = m0 + mt * 16 + (lane & 15);
        asel[mt] = (arow[mt] >> 1) & 3;
    }
    int brow_f[2], bsel[2], bkh = (lane >> 3) & 1;
#pragma unroll
    for (int np = 0; np < 2; np++) {
        brow_f[np] = n0 + np * 16 + ((lane >> 4) << 3) + (lane & 7);
        bsel[np] = (brow_f[np] >> 1) & 3;
    }

#pragma unroll
    for (int c = 0; c < 3; c++) {
        load_chunk(sb + c * STAGE_BYTES, tid, c, Ah, Al, Bh, Bl, brow, bcol, K);
        CP_COMMIT();
    }

    for (int c = 0; c < NCHUNK; c++) {
        const uint32_t so = sb + (c & (NSTAGE - 1)) * STAGE_BYTES;
        CP_WAIT2();
        __syncthreads();

#pragma unroll
        for (int ks = 0; ks < 2; ks++) {
            uint32_t afh[4][4], afl[4][4], bfh[2][4], bfl[2][4];
#pragma unroll
            for (int mt = 0; mt < 4; mt++) {
                int c16 = (ks << 1) + (lane >> 4);
                uint32_t a = so + arow[mt] * 64 + ((c16 ^ asel[mt]) << 4);
                ldsm4(afh[mt], a);
                ldsm4(afl[mt], a + SUB_BYTES);
            }
#pragma unroll
            for (int np = 0; np < 2; np++) {
                int c16 = (ks << 1) + bkh;
                uint32_t b = so + 2 * SUB_BYTES + brow_f[np] * 64 + ((c16 ^ bsel[np]) << 4);
                ldsm4(bfh[np], b);
                ldsm4(bfl[np], b + SUB_BYTES);
            }
#pragma unroll
            for (int mt = 0; mt < 4; mt++)
#pragma unroll
                for (int nt = 0; nt < 4; nt++) {
                    uint32_t* bh2 = &bfh[nt >> 1][(nt & 1) << 1];
                    uint32_t* bl2 = &bfl[nt >> 1][(nt & 1) << 1];
                    mma16816(acc[mt][nt], afh[mt], bh2);
                    mma16816(acc[mt][nt], afh[mt], bl2);
                    mma16816(acc[mt][nt], afl[mt], bh2);
                }
        }

        const int cn = c + 3;
        if (cn < NCHUNK)
            load_chunk(sb + (cn & (NSTAGE - 1)) * STAGE_BYTES, tid, cn,
                       Ah, Al, Bh, Bl, brow, bcol, K);
        CP_COMMIT();
    }

#pragma unroll
    for (int mt = 0; mt < 4; mt++) {
        int r0 = brow + m0 + mt * 16 + (lane >> 2);
#pragma unroll
        for (int nt = 0; nt < 4; nt++) {
            int col = bcol + n0 + nt * 8 + ((lane & 3) << 1);
            float2 bv = *(const float2*)(bias + col);
            float v0 = acc[mt][nt][0] + bv.x, v1 = acc[mt][nt][1] + bv.y;
            float v2 = acc[mt][nt][2] + bv.x, v3 = acc[mt][nt][3] + bv.y;
            if (SPLIT_OUT) {
                *(uint32_t*)(Ch + (size_t)r0 * N + col)       = pk_bf2(v0, v1);
                *(uint32_t*)(Ch + (size_t)(r0 + 8) * N + col) = pk_bf2(v2, v3);
                *(uint32_t*)(Cl + (size_t)r0 * N + col) =
                    pk_bf2(v0 - bf16_rt(v0), v1 - bf16_rt(v1));
                *(uint32_t*)(Cl + (size_t)(r0 + 8) * N + col) =
                    pk_bf2(v2 - bf16_rt(v2), v3 - bf16_rt(v3));
            } else {
                *(float2*)(C + (size_t)r0 * N + col)       = make_float2(v0, v1);
                *(float2*)(C + (size_t)(r0 + 8) * N + col) = make_float2(v2, v3);
            }
        }
    }
}

// ---------------------------------------------------------------------------
// HMMA flash attention (causal), bf16 hi/lo split inputs, fp32 softmax.
// CTA: 128 q-rows x (b,h); 8 warps x 16 rows. K-tiles of 64, double-buffered.
// smem: Qh 16K | Ql 16K | stage{0,1}: Kh 8K | Kl 8K | Vh 8K | Vl 8K  = 96 KB
// R7: __launch_bounds__(256,2) -> 128-reg cap, 2 CTAs/SM (16 warps).
// ---------------------------------------------------------------------------
#define ATT_SQL   16384
#define ATT_STG   32768
#define ATT_DSMEM (ATT_STG + 2 * 32768)   // 96 KB
#define SCL 0.1803368801111204f           // 0.125 * log2(e)

__device__ __forceinline__ void att_load_kv(
    uint32_t sb, int st, int tid, int krow0g, int qcol,
    const __nv_bfloat16* __restrict__ qh, const __nv_bfloat16* __restrict__ ql)
{
    const uint32_t so = sb + ATT_STG + st * 32768;
#pragma unroll
    for (int p = 0; p < 2; p++) {
        int i   = tid + (p << 8);
        int row = i >> 3;
        int c16 = i & 7;
        uint32_t dst = so + row * 128 + ((c16 ^ (row & 7)) << 4);
        size_t srcK = (size_t)(krow0g + row) * TC + Dm + qcol + (c16 << 3);
        size_t srcV = srcK + Dm;
        CP_ASYNC16(dst,         qh + srcK);
        CP_ASYNC16(dst + 8192,  ql + srcK);
        CP_ASYNC16(dst + 16384, qh + srcV);
        CP_ASYNC16(dst + 24576, ql + srcV);
    }
}

__global__ __launch_bounds__(256, 2)
void attn_hmma(const __nv_bfloat16* __restrict__ qh, const __nv_bfloat16* __restrict__ ql,
               __nv_bfloat16* __restrict__ oh, __nv_bfloat16* __restrict__ ol)
{
    extern __shared__ char smem_raw[];
    const uint32_t sb = smem_u32(smem_raw);
    const int tid  = threadIdx.x;
    const int wid  = tid >> 5;
    const int lane = tid & 31;
    const int qt   = (int)(gridDim.x - 1u - blockIdx.x);   // heavy tiles first
    const int h    = blockIdx.y;
    const int b    = blockIdx.z;
    const int qrow0 = b * Sn + qt * 128;   // global row base
    const int qcol  = h * DKc;

    // ---- load Q tile (hi/lo) + first KV stage, one commit group ----
#pragma unroll
    for (int p = 0; p < 4; p++) {
        int i   = tid + (p << 8);
        int row = i >> 3;
        int c16 = i & 7;
        uint32_t dst = sb + row * 128 + ((c16 ^ (row & 7)) << 4);
        size_t src = (size_t)(qrow0 + row) * TC + qcol + (c16 << 3);
        CP_ASYNC16(dst,           qh + src);
        CP_ASYNC16(dst + ATT_SQL, ql + src);
    }
    att_load_kv(sb, 0, tid, b * Sn, qcol, qh, ql);
    CP_COMMIT();

    const int m0 = wid << 4;           // warp's q-row base (0..112)
    const int ar = m0 + (lane & 15);   // A ldsm row
    const int asw = ar & 7;
    const int bkh = (lane >> 3) & 1;
    const int vg  = lane >> 3;

    float o[8][4];
#pragma unroll
    for (int nt = 0; nt < 8; nt++)
#pragma unroll
        for (int e = 0; e < 4; e++) o[nt][e] = 0.f;
    float mrow0 = -1e30f, mrow1 = -1e30f, lrow0 = 0.f, lrow1 = 0.f;

    const int njt = 2 * (qt + 1);
    const int gr0 = qt * 128 + m0 + (lane >> 2);   // within-sequence q index
    const int gr1 = gr0 + 8;

    for (int jt = 0; jt < njt; jt++) {
        const int cur = jt & 1;
        if (jt + 1 < njt) {
            att_load_kv(sb, cur ^ 1, tid, b * Sn + (jt + 1) * 64, qcol, qh, ql);
            CP_COMMIT();
            CP_WAIT1();
        } else {
            CP_WAIT0();
        }
        __syncthreads();

        const uint32_t soK = sb + ATT_STG + cur * 32768;
        const uint32_t soV = soK + 16384;

        // ---- S = Q K^T (3-term split) ----
        float s[8][4];
#pragma unroll
        for (int nt = 0; nt < 8; nt++)
#pragma unroll
            for (int e = 0; e < 4; e++) s[nt][e] = 0.f;

#pragma unroll
        for (int ks = 0; ks < 4; ks++) {
            uint32_t ah_[4], al_[4];
            uint32_t aaddr = sb + ar * 128 + ((((ks << 1) + (lane >> 4)) ^ asw) << 4);
            ldsm4(ah_, aaddr);
            ldsm4(al_, aaddr + ATT_SQL);
#pragma unroll
            for (int np = 0; np < 4; np++) {
                int brw = (np << 4) + ((lane >> 4) << 3) + (lane & 7);
                uint32_t baddr = soK + brw * 128 + ((((ks << 1) + bkh) ^ (brw & 7)) << 4);
                uint32_t bh_[4], bl_[4];
                ldsm4(bh_, baddr);
                ldsm4(bl_, baddr + 8192);
#pragma unroll
                for (int q = 0; q < 2; q++) {
                    float* sf = s[np * 2 + q];
                    mma16816(sf, ah_, &bh_[q << 1]);
                    mma16816(sf, ah_, &bl_[q << 1]);
                    mma16816(sf, al_, &bh_[q << 1]);
                }
            }
        }

        // ---- scale (exp2 domain), causal mask ----
        const bool diag = (jt >= 2 * qt);
        const int kbase = jt * 64 + ((lane & 3) << 1);
#pragma unroll
        for (int nt = 0; nt < 8; nt++) {
#pragma unroll
            for (int e = 0; e < 4; e++) s[nt][e] *= SCL;
            if (diag) {
                int kc = kbase + nt * 8;
                if (kc     > gr0) s[nt][0] = -1e30f;
                if (kc + 1 > gr0) s[nt][1] = -1e30f;
                if (kc     > gr1) s[nt][2] = -1e30f;
                if (kc + 1 > gr1) s[nt][3] = -1e30f;
            }
        }

        // ---- online softmax (rows r0, r1) ----
        float mx0 = -1e30f, mx1 = -1e30f;
#pragma unroll
        for (int nt = 0; nt < 8; nt++) {
            mx0 = fmaxf(mx0, fmaxf(s[nt][0], s[nt][1]));
            mx1 = fmaxf(mx1, fmaxf(s[nt][2], s[nt][3]));
        }
        mx0 = fmaxf(mx0, __shfl_xor_sync(0xffffffffu, mx0, 1));
        mx0 = fmaxf(mx0, __shfl_xor_sync(0xffffffffu, mx0, 2));
        mx1 = fmaxf(mx1, __shfl_xor_sync(0xffffffffu, mx1, 1));
        mx1 = fmaxf(mx1, __shfl_xor_sync(0xffffffffu, mx1, 2));
        float mn0 = fmaxf(mrow0, mx0), mn1 = fmaxf(mrow1, mx1);
        float c0 = ex2(mrow0 - mn0), c1 = ex2(mrow1 - mn1);
        mrow0 = mn0; mrow1 = mn1;
        float sum0 = 0.f, sum1 = 0.f;
#pragma unroll
        for (int nt = 0; nt < 8; nt++) {
            s[nt][0] = ex2(s[nt][0] - mn0); sum0 += s[nt][0];
            s[nt][1] = ex2(s[nt][1] - mn0); sum0 += s[nt][1];
            s[nt][2] = ex2(s[nt][2] - mn1); sum1 += s[nt][2];
            s[nt][3] = ex2(s[nt][3] - mn1); sum1 += s[nt][3];
        }
        sum0 += __shfl_xor_sync(0xffffffffu, sum0, 1);
        sum0 += __shfl_xor_sync(0xffffffffu, sum0, 2);
        sum1 += __shfl_xor_sync(0xffffffffu, sum1, 1);
        sum1 += __shfl_xor_sync(0xffffffffu, sum1, 2);
        lrow0 = lrow0 * c0 + sum0;
        lrow1 = lrow1 * c1 + sum1;
#pragma unroll
        for (int nt = 0; nt < 8; nt++) {
            o[nt][0] *= c0; o[nt][1] *= c0;
            o[nt][2] *= c1; o[nt][3] *= c1;
        }

        // ---- O += P V (P split hi/lo; V^T via ldmatrix.trans) ----
#pragma unroll
        for (int ks = 0; ks < 4; ks++) {
            float* pa = s[ks * 2];
            float* pb = s[ks * 2 + 1];
            uint32_t pah[4], pal[4];
            pah[0] = pk_bf2(pa[0], pa[1]);
            pah[1] = pk_bf2(pa[2], pa[3]);
            pah[2] = pk_bf2(pb[0], pb[1]);
            pah[3] = pk_bf2(pb[2], pb[3]);
            pal[0] = pk_bf2(pa[0] - bf16_rt(pa[0]), pa[1] - bf16_rt(pa[1]));
            pal[1] = pk_bf2(pa[2] - bf16_rt(pa[2]), pa[3] - bf16_rt(pa[3]));
            pal[2] = pk_bf2(pb[0] - bf16_rt(pb[0]), pb[1] - bf16_rt(pb[1]));
            pal[3] = pk_bf2(pb[2] - bf16_rt(pb[2]), pb[3] - bf16_rt(pb[3]));

            int vrow = (ks << 4) + ((vg & 1) << 3) + (lane & 7);
            int vsw  = vrow & 7;
#pragma unroll
            for (int np = 0; np < 4; np++) {
                int gran = (np << 1) + (vg >> 1);
                uint32_t vaddr = soV + vrow * 128 + ((gran ^ vsw) << 4);
                uint32_t vh_[4], vl_[4];
                ldsm4t(vh_, vaddr);
                ldsm4t(vl_, vaddr + 8192);
#pragma unroll
                for (int q = 0; q < 2; q++) {
                    float* of = o[np * 2 + q];
                    mma16816(of, pah, &vh_[q << 1]);
                    mma16816(of, pal, &vh_[q << 1]);
                    mma16816(of, pah, &vl_[q << 1]);
                }
            }
        }
        __syncthreads();   // compute done before next stage overwrite
    }

    // ---- normalize, split hi/lo, write to out-proj A buffers ----
    float inv0 = 1.f / lrow0, inv1 = 1.f / lrow1;
    const int row0 = qrow0 + m0 + (lane >> 2);
#pragma unroll
    for (int nt = 0; nt < 8; nt++) {
        int col = qcol + nt * 8 + ((lane & 3) << 1);
        float v0 = o[nt][0] * inv0, v1 = o[nt][1] * inv0;
        float v2 = o[nt][2] * inv1, v3 = o[nt][3] * inv1;
        *(uint32_t*)(oh + (size_t)row0 * Dm + col)       = pk_bf2(v0, v1);
        *(uint32_t*)(oh + (size_t)(row0 + 8) * Dm + col) = pk_bf2(v2, v3);
        *(uint32_t*)(ol + (size_t)row0 * Dm + col) =
            pk_bf2(v0 - bf16_rt(v0), v1 - bf16_rt(v1));
        *(uint32_t*)(ol + (size_t)(row0 + 8) * Dm + col) =
            pk_bf2(v2 - bf16_rt(v2), v3 - bf16_rt(v3));
    }
}

// ---------------------------------------------------------------------------
extern "C" void kernel_launch(void* const* d_in, const int* in_sizes, int n_in,
                              void* d_out, int out_size)
{
    const float* x     = (const float*)d_in[0];
    // d_in[1] = causal mask (int32) — causality hardcoded, unused
    const float* w_qkv = (const float*)d_in[2];
    const float* b_qkv = (const float*)d_in[3];
    const float* w_out = (const float*)d_in[4];
    const float* b_out = (const float*)d_in[5];
    float* out = (float*)d_out;

    __nv_bfloat16 *qh, *ql, *ah, *al, *bh, *bl;
    cudaGetSymbolAddress((void**)&qh, g_qh);
    cudaGetSymbolAddress((void**)&ql, g_ql);
    cudaGetSymbolAddress((void**)&ah, g_ah);
    cudaGetSymbolAddress((void**)&al, g_al);
    cudaGetSymbolAddress((void**)&bh, g_bh);
    cudaGetSymbolAddress((void**)&bl, g_bl);

    cudaFuncSetAttribute(gemm_bf16x3<1>, cudaFuncAttributeMaxDynamicSharedMemorySize,
                         GEMM_DSMEM);
    cudaFuncSetAttribute(gemm_bf16x3<0>, cudaFuncAttributeMaxDynamicSharedMemorySize,
                         GEMM_DSMEM);
    cudaFuncSetAttribute(attn_hmma, cudaFuncAttributeMaxDynamicSharedMemorySize,
                         ATT_DSMEM);

    // 1) operand prep for QKV gemm
    transpose_split_kernel<<<dim3(TC / 32, Dm / 32), dim3(32, 8)>>>(w_qkv, bh, bl, Dm, TC);
    split_kernel<<<(Mrows * Dm / 4 + 255) / 256, 256>>>(x, ah, al, Mrows * Dm / 4);

    // 2) QKV projection -> split bf16 qkv (no fp32 intermediate)
    gemm_bf16x3<1><<<dim3(TC / 128, Mrows / 128), 256, GEMM_DSMEM>>>(
        ah, al, bh, bl, b_qkv, nullptr, qh, ql, TC, Dm);

    // 3) causal flash attention (HMMA, 2 CTAs/SM) -> split bf16 attn out
    attn_hmma<<<dim3(Sn / 128, Hn, Bn), 256, ATT_DSMEM>>>(qh, ql, ah, al);

    // 4) operand prep for out gemm (weights only; A comes from attention)
    transpose_split_kernel<<<dim3(Dm / 32, Dm / 32), dim3(32, 8)>>>(w_out, bh, bl, Dm, Dm);

    // 5) output projection -> fp32 out
    gemm_bf16x3<0><<<dim3(Dm / 128, Mrows / 128), 256, GEMM_DSMEM>>>(
        ah, al, bh, bl, b_out, out, nullptr, nullptr, Dm, Dm);
}

// round 10
// speedup vs baseline: 1.0177x; 1.0177x over previous
#include <cuda_runtime.h>
#include <cuda_bf16.h>
#include <cstdint>

// Problem constants
#define Bn   2
#define Sn   2048
#define Dm   1024
#define Hn   16
#define DKc  64
#define Mrows 4096          // B*S
#define TC   3072           // 3*Dm

// Scratch (allocation-free: __device__ globals)
__device__ __nv_bfloat16 g_qh[(size_t)Mrows * TC];  // qkv hi
__device__ __nv_bfloat16 g_ql[(size_t)Mrows * TC];  // qkv lo
__device__ __nv_bfloat16 g_ah[(size_t)Mrows * Dm];  // A hi (x-split, then attn out)
__device__ __nv_bfloat16 g_al[(size_t)Mrows * Dm];  // A lo
__device__ __nv_bfloat16 g_bh[(size_t)TC * Dm];     // B^T hi
__device__ __nv_bfloat16 g_bl[(size_t)TC * Dm];     // B^T lo

// ---------------------------------------------------------------------------
// PTX helpers (baseline-PTX only: cp.async, ldmatrix, mma.sync)
// ---------------------------------------------------------------------------
__device__ __forceinline__ uint32_t smem_u32(const void* p) {
    return (uint32_t)__cvta_generic_to_shared(p);
}
#define CP_ASYNC16(dst, src) \
    asm volatile("cp.async.cg.shared.global [%0], [%1], 16;" :: "r"(dst), "l"(src))
#define CP_COMMIT() asm volatile("cp.async.commit_group;" ::: "memory")
#define CP_WAIT1()  asm volatile("cp.async.wait_group 1;" ::: "memory")
#define CP_WAIT0()  asm volatile("cp.async.wait_group 0;" ::: "memory")

__device__ __forceinline__ void ldsm4(uint32_t* r, uint32_t addr) {
    asm volatile("ldmatrix.sync.aligned.m8n8.x4.shared.b16 {%0,%1,%2,%3}, [%4];"
        : "=r"(r[0]), "=r"(r[1]), "=r"(r[2]), "=r"(r[3]) : "r"(addr));
}
__device__ __forceinline__ void ldsm4t(uint32_t* r, uint32_t addr) {
    asm volatile("ldmatrix.sync.aligned.m8n8.x4.trans.shared.b16 {%0,%1,%2,%3}, [%4];"
        : "=r"(r[0]), "=r"(r[1]), "=r"(r[2]), "=r"(r[3]) : "r"(addr));
}
__device__ __forceinline__ void mma16816(float* d, const uint32_t* a, const uint32_t* b) {
    asm volatile(
        "mma.sync.aligned.m16n8k16.row.col.f32.bf16.bf16.f32 "
        "{%0,%1,%2,%3}, {%4,%5,%6,%7}, {%8,%9}, {%0,%1,%2,%3};"
        : "+f"(d[0]), "+f"(d[1]), "+f"(d[2]), "+f"(d[3])
        : "r"(a[0]), "r"(a[1]), "r"(a[2]), "r"(a[3]), "r"(b[0]), "r"(b[1]));
}
__device__ __forceinline__ float ex2(float x) {
    float r; asm("ex2.approx.f32 %0, %1;" : "=f"(r) : "f"(x)); return r;
}
// pack two f32 -> bf16x2 (first arg in low half)
__device__ __forceinline__ uint32_t pk_bf2(float lo, float hi) {
    uint32_t r;
    asm("cvt.rn.bf16x2.f32 %0, %1, %2;" : "=r"(r) : "f"(hi), "f"(lo));
    return r;
}
__device__ __forceinline__ float bf16_rt(float v) {   // round-trip through bf16
    return __bfloat162float(__float2bfloat16(v));
}

// ---------------------------------------------------------------------------
// fp32 -> bf16 hi/lo split (straight copy)
// ---------------------------------------------------------------------------
__global__ void split_kernel(const float* __restrict__ in,
                             __nv_bfloat16* __restrict__ hi,
                             __nv_bfloat16* __restrict__ lo, int n4)
{
    int i = blockIdx.x * blockDim.x + threadIdx.x;
    if (i >= n4) return;
    float4 v = ((const float4*)in)[i];
    float vv[4] = {v.x, v.y, v.z, v.w};
    uint32_t h2[2], l2[2];
#pragma unroll
    for (int p = 0; p < 2; p++) {
        h2[p] = pk_bf2(vv[2*p], vv[2*p+1]);
        __nv_bfloat162 hh = *(__nv_bfloat162*)&h2[p];
        float f0 = __bfloat162float(hh.x), f1 = __bfloat162float(hh.y);
        l2[p] = pk_bf2(vv[2*p] - f0, vv[2*p+1] - f1);
    }
    ((uint32_t*)hi)[2*i]   = h2[0];
    ((uint32_t*)hi)[2*i+1] = h2[1];
    ((uint32_t*)lo)[2*i]   = l2[0];
    ((uint32_t*)lo)[2*i+1] = l2[1];
}

// ---------------------------------------------------------------------------
// fp32 [K][N] -> bf16 hi/lo [N][K] (transpose + split), 32x32 tiles
// ---------------------------------------------------------------------------
__global__ void transpose_split_kernel(const float* __restrict__ in,
                                       __nv_bfloat16* __restrict__ hi,
                                       __nv_bfloat16* __restrict__ lo,
                                       int K, int N)
{
    __shared__ float t[32][33];
    int bx = blockIdx.x << 5;
    int by = blockIdx.y << 5;
    int x = threadIdx.x;
    int y = threadIdx.y;
#pragma unroll
    for (int i = 0; i < 32; i += 8)
        t[y + i][x] = in[(size_t)(by + y + i) * N + bx + x];
    __syncthreads();
#pragma unroll
    for (int i = 0; i < 32; i += 8) {
        float v = t[x][y + i];
        float h = bf16_rt(v);
        size_t o = (size_t)(bx + y + i) * K + by + x;
        hi[o] = __float2bfloat16(v);
        lo[o] = __float2bfloat16(v - h);
    }
}

// ---------------------------------------------------------------------------
// HMMA bf16-split GEMM: C[M,N] = A[M,K] @ BT[N,K]^T + bias
// 128x128x32 CTA tile, 8 warps of 64x32.
// R9: 3-stage pipeline (96 KB) + 2 CTAs/SM.
// ---------------------------------------------------------------------------
#define SUB_BYTES  8192
#define STAGE_BYTES (4 * SUB_BYTES)
#define NSTAGE 3
#define GEMM_DSMEM (NSTAGE * STAGE_BYTES)  // 96 KB

__device__ __forceinline__ void load_chunk(
    uint32_t so, int tid, int chunk,
    const __nv_bfloat16* __restrict__ Ah, const __nv_bfloat16* __restrict__ Al,
    const __nv_bfloat16* __restrict__ Bh, const __nv_bfloat16* __restrict__ Bl,
    int brow, int bcol, int K)
{
    const int k0 = chunk << 5;
#pragma unroll
    for (int p = 0; p < 2; p++) {
        int r   = (tid >> 2) + (p << 6);
        int c16 = tid & 3;
        uint32_t dst = so + r * 64 + ((c16 ^ ((r >> 1) & 3)) << 4);
        size_t ga = (size_t)(brow + r) * K + k0 + (c16 << 3);
        size_t gb = (size_t)(bcol + r) * K + k0 + (c16 << 3);
        CP_ASYNC16(dst,                 Ah + ga);
        CP_ASYNC16(dst + SUB_BYTES,     Al + ga);
        CP_ASYNC16(dst + 2 * SUB_BYTES, Bh + gb);
        CP_ASYNC16(dst + 3 * SUB_BYTES, Bl + gb);
    }
}

template<int SPLIT_OUT>
__global__ __launch_bounds__(256, 2)
void gemm_bf16x3(const __nv_bfloat16* __restrict__ Ah, const __nv_bfloat16* __restrict__ Al,
                 const __nv_bfloat16* __restrict__ Bh, const __nv_bfloat16* __restrict__ Bl,
                 const float* __restrict__ bias, float* __restrict__ C,
                 __nv_bfloat16* __restrict__ Ch, __nv_bfloat16* __restrict__ Cl,
                 int N, int K)
{
    extern __shared__ char dsmem_raw[];
    const uint32_t sb = smem_u32(dsmem_raw);

    const int tid  = threadIdx.x;
    const int wid  = tid >> 5;
    const int lane = tid & 31;
    const int brow = blockIdx.y << 7;
    const int bcol = blockIdx.x << 7;
    const int NCHUNK = K >> 5;

    const int m0 = (wid & 1) << 6;
    const int n0 = (wid >> 1) << 5;

    float acc[4][4][4];
#pragma unroll
    for (int mt = 0; mt < 4; mt++)
#pragma unroll
        for (int nt = 0; nt < 4; nt++)
#pragma unroll
            for (int e = 0; e < 4; e++) acc[mt][nt][e] = 0.f;

    int arow[4], asel[4];
#pragma unroll
    for (int mt = 0; mt < 4; mt++) {
        arow[mt] = m0 + mt * 16 + (lane & 15);
        asel[mt] = (arow[mt] >> 1) & 3;
    }
    int brow_f[2], bsel[2], bkh = (lane >> 3) & 1;
#pragma unroll
    for (int np = 0; np < 2; np++) {
        brow_f[np] = n0 + np * 16 + ((lane >> 4) << 3) + (lane & 7);
        bsel[np] = (brow_f[np] >> 1) & 3;
    }

    // prologue: chunks 0,1 (one group each)
#pragma unroll
    for (int c = 0; c < 2; c++) {
        load_chunk(sb + c * STAGE_BYTES, tid, c, Ah, Al, Bh, Bl, brow, bcol, K);
        CP_COMMIT();
    }

    int st = 0;                       // stage of chunk c (c % 3)
    for (int c = 0; c < NCHUNK; c++) {
        const uint32_t so = sb + st * STAGE_BYTES;
        CP_WAIT1();                   // chunk c resident (one group committed/iter)
        __syncthreads();              // all warps done computing chunk c-1

        // prefetch chunk c+2 into stage (c+2)%3 (last used by chunk c-1)
        const int cn = c + 2;
        int stn = st + 2; if (stn >= 3) stn -= 3;
        if (cn < NCHUNK)
            load_chunk(sb + stn * STAGE_BYTES, tid, cn, Ah, Al, Bh, Bl, brow, bcol, K);
        CP_COMMIT();                  // real or empty group — keeps count uniform

#pragma unroll
        for (int ks = 0; ks < 2; ks++) {
            uint32_t afh[4][4], afl[4][4], bfh[2][4], bfl[2][4];
#pragma unroll
            for (int mt = 0; mt < 4; mt++) {
                int c16 = (ks << 1) + (lane >> 4);
                uint32_t a = so + arow[mt] * 64 + ((c16 ^ asel[mt]) << 4);
                ldsm4(afh[mt], a);
                ldsm4(afl[mt], a + SUB_BYTES);
            }
#pragma unroll
            for (int np = 0; np < 2; np++) {
                int c16 = (ks << 1) + bkh;
                uint32_t b = so + 2 * SUB_BYTES + brow_f[np] * 64 + ((c16 ^ bsel[np]) << 4);
                ldsm4(bfh[np], b);
                ldsm4(bfl[np], b + SUB_BYTES);
            }
#pragma unroll
            for (int mt = 0; mt < 4; mt++)
#pragma unroll
                for (int nt = 0; nt < 4; nt++) {
                    uint32_t* bh2 = &bfh[nt >> 1][(nt & 1) << 1];
                    uint32_t* bl2 = &bfl[nt >> 1][(nt & 1) << 1];
                    mma16816(acc[mt][nt], afh[mt], bh2);
                    mma16816(acc[mt][nt], afh[mt], bl2);
                    mma16816(acc[mt][nt], afl[mt], bh2);
                }
        }
        if (++st == 3) st = 0;
    }

#pragma unroll
    for (int mt = 0; mt < 4; mt++) {
        int r0 = brow + m0 + mt * 16 + (lane >> 2);
#pragma unroll
        for (int nt = 0; nt < 4; nt++) {
            int col = bcol + n0 + nt * 8 + ((lane & 3) << 1);
            float2 bv = *(const float2*)(bias + col);
            float v0 = acc[mt][nt][0] + bv.x, v1 = acc[mt][nt][1] + bv.y;
            float v2 = acc[mt][nt][2] + bv.x, v3 = acc[mt][nt][3] + bv.y;
            if (SPLIT_OUT) {
                *(uint32_t*)(Ch + (size_t)r0 * N + col)       = pk_bf2(v0, v1);
                *(uint32_t*)(Ch + (size_t)(r0 + 8) * N + col) = pk_bf2(v2, v3);
                *(uint32_t*)(Cl + (size_t)r0 * N + col) =
                    pk_bf2(v0 - bf16_rt(v0), v1 - bf16_rt(v1));
                *(uint32_t*)(Cl + (size_t)(r0 + 8) * N + col) =
                    pk_bf2(v2 - bf16_rt(v2), v3 - bf16_rt(v3));
            } else {
                *(float2*)(C + (size_t)r0 * N + col)       = make_float2(v0, v1);
                *(float2*)(C + (size_t)(r0 + 8) * N + col) = make_float2(v2, v3);
            }
        }
    }
}

// ---------------------------------------------------------------------------
// HMMA flash attention (causal), bf16 hi/lo split inputs, fp32 softmax.
// CTA: 128 q-rows x (b,h); 8 warps x 16 rows. K-tiles of 64, double-buffered.
// R9: Q fragments hoisted to registers (loaded once); fully-masked warps skip
// compute on the odd diagonal tile; occ=1 (R8 showed occ2 is perf-neutral).
// ---------------------------------------------------------------------------
#define ATT_SQL   16384
#define ATT_STG   32768
#define ATT_DSMEM (ATT_STG + 2 * 32768)   // 96 KB
#define SCL 0.1803368801111204f           // 0.125 * log2(e)

__device__ __forceinline__ void att_load_kv(
    uint32_t sb, int st, int tid, int krow0g, int qcol,
    const __nv_bfloat16* __restrict__ qh, const __nv_bfloat16* __restrict__ ql)
{
    const uint32_t so = sb + ATT_STG + st * 32768;
#pragma unroll
    for (int p = 0; p < 2; p++) {
        int i   = tid + (p << 8);
        int row = i >> 3;
        int c16 = i & 7;
        uint32_t dst = so + row * 128 + ((c16 ^ (row & 7)) << 4);
        size_t srcK = (size_t)(krow0g + row) * TC + Dm + qcol + (c16 << 3);
        size_t srcV = srcK + Dm;
        CP_ASYNC16(dst,         qh + srcK);
        CP_ASYNC16(dst + 8192,  ql + srcK);
        CP_ASYNC16(dst + 16384, qh + srcV);
        CP_ASYNC16(dst + 24576, ql + srcV);
    }
}

__global__ __launch_bounds__(256, 1)
void attn_hmma(const __nv_bfloat16* __restrict__ qh, const __nv_bfloat16* __restrict__ ql,
               __nv_bfloat16* __restrict__ oh, __nv_bfloat16* __restrict__ ol)
{
    extern __shared__ char smem_raw[];
    const uint32_t sb = smem_u32(smem_raw);
    const int tid  = threadIdx.x;
    const int wid  = tid >> 5;
    const int lane = tid & 31;
    const int qt   = (int)(gridDim.x - 1u - blockIdx.x);   // heavy tiles first
    const int h    = blockIdx.y;
    const int b    = blockIdx.z;
    const int qrow0 = b * Sn + qt * 128;   // global row base
    const int qcol  = h * DKc;

    // ---- load Q tile (hi/lo) + first KV stage, one commit group ----
#pragma unroll
    for (int p = 0; p < 4; p++) {
        int i   = tid + (p << 8);
        int row = i >> 3;
        int c16 = i & 7;
        uint32_t dst = sb + row * 128 + ((c16 ^ (row & 7)) << 4);
        size_t src = (size_t)(qrow0 + row) * TC + qcol + (c16 << 3);
        CP_ASYNC16(dst,           qh + src);
        CP_ASYNC16(dst + ATT_SQL, ql + src);
    }
    att_load_kv(sb, 0, tid, b * Sn, qcol, qh, ql);
    CP_COMMIT();

    const int m0 = wid << 4;           // warp's q-row base (0..112)
    const int ar = m0 + (lane & 15);   // A ldsm row
    const int asw = ar & 7;
    const int bkh = (lane >> 3) & 1;
    const int vg  = lane >> 3;

    uint32_t qfh[4][4], qfl[4][4];     // hoisted Q fragments (loaded at jt==0)

    float o[8][4];
#pragma unroll
    for (int nt = 0; nt < 8; nt++)
#pragma unroll
        for (int e = 0; e < 4; e++) o[nt][e] = 0.f;
    float mrow0 = -1e30f, mrow1 = -1e30f, lrow0 = 0.f, lrow1 = 0.f;

    const int njt = 2 * (qt + 1);
    const int gr0 = qt * 128 + m0 + (lane >> 2);   // within-sequence q index
    const int gr1 = gr0 + 8;

    for (int jt = 0; jt < njt; jt++) {
        const int cur = jt & 1;
        if (jt + 1 < njt) {
            att_load_kv(sb, cur ^ 1, tid, b * Sn + (jt + 1) * 64, qcol, qh, ql);
            CP_COMMIT();
            CP_WAIT1();
        } else {
            CP_WAIT0();
        }
        __syncthreads();

        if (jt == 0) {   // Q now resident — load fragments once
#pragma unroll
            for (int ks = 0; ks < 4; ks++) {
                uint32_t aaddr = sb + ar * 128 + ((((ks << 1) + (lane >> 4)) ^ asw) << 4);
                ldsm4(qfh[ks], aaddr);
                ldsm4(qfl[ks], aaddr + ATT_SQL);
            }
        }

        // fully-masked warp on the odd diagonal tile: contribution provably 0
        const bool skipw = (jt == 2 * qt + 1) && (m0 < 64);
        if (!skipw) {
            const uint32_t soK = sb + ATT_STG + cur * 32768;
            const uint32_t soV = soK + 16384;

            // ---- S = Q K^T (3-term split) ----
            float s[8][4];
#pragma unroll
            for (int nt = 0; nt < 8; nt++)
#pragma unroll
                for (int e = 0; e < 4; e++) s[nt][e] = 0.f;

#pragma unroll
            for (int ks = 0; ks < 4; ks++) {
#pragma unroll
                for (int np = 0; np < 4; np++) {
                    int brw = (np << 4) + ((lane >> 4) << 3) + (lane & 7);
                    uint32_t baddr = soK + brw * 128 + ((((ks << 1) + bkh) ^ (brw & 7)) << 4);
                    uint32_t bh_[4], bl_[4];
                    ldsm4(bh_, baddr);
                    ldsm4(bl_, baddr + 8192);
#pragma unroll
                    for (int q = 0; q < 2; q++) {
                        float* sf = s[np * 2 + q];
                        mma16816(sf, qfh[ks], &bh_[q << 1]);
                        mma16816(sf, qfh[ks], &bl_[q << 1]);
                        mma16816(sf, qfl[ks], &bh_[q << 1]);
                    }
                }
            }

            // ---- scale (exp2 domain), causal mask ----
            const bool diag = (jt >= 2 * qt);
            const int kbase = jt * 64 + ((lane & 3) << 1);
#pragma unroll
            for (int nt = 0; nt < 8; nt++) {
#pragma unroll
                for (int e = 0; e < 4; e++) s[nt][e] *= SCL;
                if (diag) {
                    int kc = kbase + nt * 8;
                    if (kc     > gr0) s[nt][0] = -1e30f;
                    if (kc + 1 > gr0) s[nt][1] = -1e30f;
                    if (kc     > gr1) s[nt][2] = -1e30f;
                    if (kc + 1 > gr1) s[nt][3] = -1e30f;
                }
            }

            // ---- online softmax (rows r0, r1) ----
            float mx0 = -1e30f, mx1 = -1e30f;
#pragma unroll
            for (int nt = 0; nt < 8; nt++) {
                mx0 = fmaxf(mx0, fmaxf(s[nt][0], s[nt][1]));
                mx1 = fmaxf(mx1, fmaxf(s[nt][2], s[nt][3]));
            }
            mx0 = fmaxf(mx0, __shfl_xor_sync(0xffffffffu, mx0, 1));
            mx0 = fmaxf(mx0, __shfl_xor_sync(0xffffffffu, mx0, 2));
            mx1 = fmaxf(mx1, __shfl_xor_sync(0xffffffffu, mx1, 1));
            mx1 = fmaxf(mx1, __shfl_xor_sync(0xffffffffu, mx1, 2));
            float mn0 = fmaxf(mrow0, mx0), mn1 = fmaxf(mrow1, mx1);
            float c0 = ex2(mrow0 - mn0), c1 = ex2(mrow1 - mn1);
            mrow0 = mn0; mrow1 = mn1;
            float sum0 = 0.f, sum1 = 0.f;
#pragma unroll
            for (int nt = 0; nt < 8; nt++) {
                s[nt][0] = ex2(s[nt][0] - mn0); sum0 += s[nt][0];
                s[nt][1] = ex2(s[nt][1] - mn0); sum0 += s[nt][1];
                s[nt][2] = ex2(s[nt][2] - mn1); sum1 += s[nt][2];
                s[nt][3] = ex2(s[nt][3] - mn1); sum1 += s[nt][3];
            }
            sum0 += __shfl_xor_sync(0xffffffffu, sum0, 1);
            sum0 += __shfl_xor_sync(0xffffffffu, sum0, 2);
            sum1 += __shfl_xor_sync(0xffffffffu, sum1, 1);
            sum1 += __shfl_xor_sync(0xffffffffu, sum1, 2);
            lrow0 = lrow0 * c0 + sum0;
            lrow1 = lrow1 * c1 + sum1;
#pragma unroll
            for (int nt = 0; nt < 8; nt++) {
                o[nt][0] *= c0; o[nt][1] *= c0;
                o[nt][2] *= c1; o[nt][3] *= c1;
            }

            // ---- O += P V (P split hi/lo; V^T via ldmatrix.trans) ----
#pragma unroll
            for (int ks = 0; ks < 4; ks++) {
                float* pa = s[ks * 2];
                float* pb = s[ks * 2 + 1];
                uint32_t pah[4], pal[4];
                pah[0] = pk_bf2(pa[0], pa[1]);
                pah[1] = pk_bf2(pa[2], pa[3]);
                pah[2] = pk_bf2(pb[0], pb[1]);
                pah[3] = pk_bf2(pb[2], pb[3]);
                pal[0] = pk_bf2(pa[0] - bf16_rt(pa[0]), pa[1] - bf16_rt(pa[1]));
                pal[1] = pk_bf2(pa[2] - bf16_rt(pa[2]), pa[3] - bf16_rt(pa[3]));
                pal[2] = pk_bf2(pb[0] - bf16_rt(pb[0]), pb[1] - bf16_rt(pb[1]));
                pal[3] = pk_bf2(pb[2] - bf16_rt(pb[2]), pb[3] - bf16_rt(pb[3]));

                int vrow = (ks << 4) + ((vg & 1) << 3) + (lane & 7);
                int vsw  = vrow & 7;
#pragma unroll
                for (int np = 0; np < 4; np++) {
                    int gran = (np << 1) + (vg >> 1);
                    uint32_t vaddr = soV + vrow * 128 + ((gran ^ vsw) << 4);
                    uint32_t vh_[4], vl_[4];
                    ldsm4t(vh_, vaddr);
                    ldsm4t(vl_, vaddr + 8192);
#pragma unroll
                    for (int q = 0; q < 2; q++) {
                        float* of = o[np * 2 + q];
                        mma16816(of, pah, &vh_[q << 1]);
                        mma16816(of, pal, &vh_[q << 1]);
                        mma16816(of, pah, &vl_[q << 1]);
                    }
                }
            }
        }
        __syncthreads();   // compute done before next stage overwrite
    }

    // ---- normalize, split hi/lo, write to out-proj A buffers ----
    float inv0 = 1.f / lrow0, inv1 = 1.f / lrow1;
    const int row0 = qrow0 + m0 + (lane >> 2);
#pragma unroll
    for (int nt = 0; nt < 8; nt++) {
        int col = qcol + nt * 8 + ((lane & 3) << 1);
        float v0 = o[nt][0] * inv0, v1 = o[nt][1] * inv0;
        float v2 = o[nt][2] * inv1, v3 = o[nt][3] * inv1;
        *(uint32_t*)(oh + (size_t)row0 * Dm + col)       = pk_bf2(v0, v1);
        *(uint32_t*)(oh + (size_t)(row0 + 8) * Dm + col) = pk_bf2(v2, v3);
        *(uint32_t*)(ol + (size_t)row0 * Dm + col) =
            pk_bf2(v0 - bf16_rt(v0), v1 - bf16_rt(v1));
        *(uint32_t*)(ol + (size_t)(row0 + 8) * Dm + col) =
            pk_bf2(v2 - bf16_rt(v2), v3 - bf16_rt(v3));
    }
}

// ---------------------------------------------------------------------------
extern "C" void kernel_launch(void* const* d_in, const int* in_sizes, int n_in,
                              void* d_out, int out_size)
{
    const float* x     = (const float*)d_in[0];
    // d_in[1] = causal mask (int32) — causality hardcoded, unused
    const float* w_qkv = (const float*)d_in[2];
    const float* b_qkv = (const float*)d_in[3];
    const float* w_out = (const float*)d_in[4];
    const float* b_out = (const float*)d_in[5];
    float* out = (float*)d_out;

    __nv_bfloat16 *qh, *ql, *ah, *al, *bh, *bl;
    cudaGetSymbolAddress((void**)&qh, g_qh);
    cudaGetSymbolAddress((void**)&ql, g_ql);
    cudaGetSymbolAddress((void**)&ah, g_ah);
    cudaGetSymbolAddress((void**)&al, g_al);
    cudaGetSymbolAddress((void**)&bh, g_bh);
    cudaGetSymbolAddress((void**)&bl, g_bl);

    cudaFuncSetAttribute(gemm_bf16x3<1>, cudaFuncAttributeMaxDynamicSharedMemorySize,
                         GEMM_DSMEM);
    cudaFuncSetAttribute(gemm_bf16x3<0>, cudaFuncAttributeMaxDynamicSharedMemorySize,
                         GEMM_DSMEM);
    cudaFuncSetAttribute(attn_hmma, cudaFuncAttributeMaxDynamicSharedMemorySize,
                         ATT_DSMEM);

    // 1) operand prep for QKV gemm
    transpose_split_kernel<<<dim3(TC / 32, Dm / 32), dim3(32, 8)>>>(w_qkv, bh, bl, Dm, TC);
    split_kernel<<<(Mrows * Dm / 4 + 255) / 256, 256>>>(x, ah, al, Mrows * Dm / 4);

    // 2) QKV projection -> split bf16 qkv (no fp32 intermediate)
    gemm_bf16x3<1><<<dim3(TC / 128, Mrows / 128), 256, GEMM_DSMEM>>>(
        ah, al, bh, bl, b_qkv, nullptr, qh, ql, TC, Dm);

    // 3) causal flash attention (HMMA) -> split bf16 attn out
    attn_hmma<<<dim3(Sn / 128, Hn, Bn), 256, ATT_DSMEM>>>(qh, ql, ah, al);

    // 4) operand prep for out gemm (weights only; A comes from attention)
    transpose_split_kernel<<<dim3(Dm / 32, Dm / 32), dim3(32, 8)>>>(w_out, bh, bl, Dm, Dm);

    // 5) output projection -> fp32 out
    gemm_bf16x3<0><<<dim3(Dm / 128, Mrows / 128), 256, GEMM_DSMEM>>>(
        ah, al, bh, bl, b_out, out, nullptr, nullptr, Dm, Dm);
}